// round 14
// baseline (speedup 1.0000x reference)
#include <cuda_runtime.h>
#include <cuda_bf16.h>
#include <cstdint>

#define BATCH  2
#define SEQ    2048
#define DMODEL 1024
#define NHEAD  16
#define HDIM   64

// ---------------------------------------------------------------------------
// Device-global scratch (allocation-free per harness rules)
// ---------------------------------------------------------------------------
static __device__ __nv_bfloat16 g_qkvh[(size_t)BATCH * SEQ * 3 * DMODEL]; // [4096,3072]
static __device__ __nv_bfloat16 g_qkvl[(size_t)BATCH * SEQ * 3 * DMODEL];
static __device__ __nv_bfloat16 g_xh[(size_t)BATCH * SEQ * DMODEL];
static __device__ __nv_bfloat16 g_xl[(size_t)BATCH * SEQ * DMODEL];
static __device__ __nv_bfloat16 g_yh[(size_t)BATCH * SEQ * DMODEL];
static __device__ __nv_bfloat16 g_yl[(size_t)BATCH * SEQ * DMODEL];
static __device__ __nv_bfloat16 g_qgh[(size_t)BATCH * SEQ * DMODEL];
static __device__ __nv_bfloat16 g_kgh[(size_t)BATCH * SEQ * DMODEL];
static __device__ __nv_bfloat16 g_wqt_h[(size_t)3 * DMODEL * DMODEL];  // [3072,1024] (N,K)
static __device__ __nv_bfloat16 g_wqt_l[(size_t)3 * DMODEL * DMODEL];
static __device__ __nv_bfloat16 g_wot_h[(size_t)DMODEL * DMODEL];      // [1024,1024]
static __device__ __nv_bfloat16 g_wot_l[(size_t)DMODEL * DMODEL];

// ---------------------------------------------------------------------------
// Baseline-PTX helpers (legal for .target sm_103 — no 'a'-only features)
// ---------------------------------------------------------------------------
__device__ __forceinline__ uint32_t smem_u32(const void* p) {
    uint32_t a;
    asm("{ .reg .u64 t; cvta.to.shared.u64 t, %1; cvt.u32.u64 %0, t; }"
        : "=r"(a) : "l"(p));
    return a;
}

#define CPA16(dst, src) \
    asm volatile("cp.async.cg.shared.global [%0], [%1], 16;" \
                 :: "r"(dst), "l"(src) : "memory")
#define CP_COMMIT() asm volatile("cp.async.commit_group;" ::: "memory")
#define CP_WAIT0()  asm volatile("cp.async.wait_group 0;" ::: "memory")
#define CP_WAIT1()  asm volatile("cp.async.wait_group 1;" ::: "memory")
#define CP_WAIT2()  asm volatile("cp.async.wait_group 2;" ::: "memory")

#define LDSM4(r, addr) \
    asm volatile("ldmatrix.sync.aligned.m8n8.x4.shared.b16 {%0,%1,%2,%3}, [%4];" \
                 : "=r"((r)[0]), "=r"((r)[1]), "=r"((r)[2]), "=r"((r)[3]) \
                 : "r"(addr))

#define LDSM4T(r, addr) \
    asm volatile("ldmatrix.sync.aligned.m8n8.x4.trans.shared.b16 {%0,%1,%2,%3}, [%4];" \
                 : "=r"((r)[0]), "=r"((r)[1]), "=r"((r)[2]), "=r"((r)[3]) \
                 : "r"(addr))

#define MMA_BF16(d, a, b) \
    asm volatile("mma.sync.aligned.m16n8k16.row.col.f32.bf16.bf16.f32 " \
                 "{%0,%1,%2,%3}, {%4,%5,%6,%7}, {%8,%9}, {%0,%1,%2,%3};" \
                 : "+f"((d)[0]), "+f"((d)[1]), "+f"((d)[2]), "+f"((d)[3]) \
                 : "r"((a)[0]), "r"((a)[1]), "r"((a)[2]), "r"((a)[3]), \
                   "r"((b)[0]), "r"((b)[1]))

__device__ __forceinline__ uint32_t pack_bf16x2(float lo, float hi) {
    __nv_bfloat162 t = __floats2bfloat162_rn(lo, hi);
    return *(uint32_t*)&t;
}

__device__ __forceinline__ float ex2f(float x) {
    float y;
    asm("ex2.approx.ftz.f32 %0, %1;" : "=f"(y) : "f"(x));
    return y;
}

// ---------------------------------------------------------------------------
// Prep kernels
// ---------------------------------------------------------------------------
__global__ __launch_bounds__(256) void cvt_hilo(const float* __restrict__ src,
                                                __nv_bfloat16* __restrict__ hi,
                                                __nv_bfloat16* __restrict__ lo)
{
    int i = (blockIdx.x * 256 + threadIdx.x) * 4;
    float4 v = *(const float4*)(src + i);
    __nv_bfloat16 h0 = __float2bfloat16(v.x);
    __nv_bfloat16 h1 = __float2bfloat16(v.y);
    __nv_bfloat16 h2 = __float2bfloat16(v.z);
    __nv_bfloat16 h3 = __float2bfloat16(v.w);
    *(uint2*)(hi + i) = make_uint2(pack_bf16x2(v.x, v.y), pack_bf16x2(v.z, v.w));
    *(uint2*)(lo + i) = make_uint2(
        pack_bf16x2(v.x - __bfloat162float(h0), v.y - __bfloat162float(h1)),
        pack_bf16x2(v.z - __bfloat162float(h2), v.w - __bfloat162float(h3)));
}

__global__ __launch_bounds__(256) void cvt_bf16(const float* __restrict__ src,
                                                __nv_bfloat16* __restrict__ dst)
{
    int i = (blockIdx.x * 256 + threadIdx.x) * 4;
    float4 v = *(const float4*)(src + i);
    *(uint2*)(dst + i) = make_uint2(pack_bf16x2(v.x, v.y), pack_bf16x2(v.z, v.w));
}

// W [K,N] fp32 -> Th/Tl [N,K] bf16 (transpose + hi/lo split)
__global__ __launch_bounds__(256) void tconv(const float* __restrict__ W,
                                             __nv_bfloat16* __restrict__ Th,
                                             __nv_bfloat16* __restrict__ Tl,
                                             int K, int N)
{
    __shared__ float t[32][33];
    const int tx = threadIdx.x, ty = threadIdx.y;
    const int k0 = blockIdx.y * 32, n0 = blockIdx.x * 32;
#pragma unroll
    for (int r = ty; r < 32; r += 8)
        t[r][tx] = W[(size_t)(k0 + r) * N + n0 + tx];
    __syncthreads();
#pragma unroll
    for (int r = ty; r < 32; r += 8) {
        float v = t[tx][r];
        __nv_bfloat16 h = __float2bfloat16(v);
        __nv_bfloat16 l = __float2bfloat16(v - __bfloat162float(h));
        Th[(size_t)(n0 + r) * K + k0 + tx] = h;
        Tl[(size_t)(n0 + r) * K + k0 + tx] = l;
    }
}

// ---------------------------------------------------------------------------
// bf16 hi/lo GEMM via mma.sync (unchanged from R9)
// ---------------------------------------------------------------------------
#define GEMM_SMEM_BYTES (3 * 65536)

template <bool BF16OUT>
__global__ __launch_bounds__(512, 1) void gemm_mma(
    const __nv_bfloat16* __restrict__ Ah, const __nv_bfloat16* __restrict__ Al,
    const __nv_bfloat16* __restrict__ Bh, const __nv_bfloat16* __restrict__ Bl,
    float* __restrict__ Cf,
    __nv_bfloat16* __restrict__ Ch, __nv_bfloat16* __restrict__ Cl,
    int N, int K)
{
    extern __shared__ char smem[];
    const uint32_t sb = smem_u32(smem);
    const int tid  = threadIdx.x;
    const int wid  = tid >> 5;
    const int lane = tid & 31;
    const int wr = wid >> 2;
    const int wc = wid & 3;
    const int row0 = blockIdx.y * 128;
    const int col0 = blockIdx.x * 128;
    const int nchunk = K / 64;

    const int lr = tid >> 3;
    const int lc = tid & 7;
    const uint32_t swoff = (uint32_t)((lr * 128 + lc * 16) ^ ((lr & 7) << 4));

    const int frow = (lane & 7) + ((lane >> 3) & 1) * 8;
    const uint32_t fxor = (uint32_t)((lane & 7) << 4);
    const uint32_t fkg  = (uint32_t)((lane >> 4) << 4);
    uint32_t offA[2], offB[2];
#pragma unroll
    for (int mt = 0; mt < 2; mt++)
        offA[mt] = (uint32_t)((wr * 32 + mt * 16 + frow) * 128);
#pragma unroll
    for (int ng = 0; ng < 2; ng++)
        offB[ng] = (uint32_t)((wc * 32 + ng * 16 + frow) * 128);

    float acc[2][4][4];
#pragma unroll
    for (int mt = 0; mt < 2; mt++)
#pragma unroll
        for (int nt = 0; nt < 4; nt++)
#pragma unroll
            for (int e = 0; e < 4; e++) acc[mt][nt][e] = 0.0f;

    auto load_chunk = [&](int stage, int kbase) {
        const uint32_t stb = sb + stage * 65536;
#pragma unroll
        for (int p = 0; p < 4; p++) {
            const __nv_bfloat16* src = (p == 0) ? Ah : (p == 1) ? Al
                                      : (p == 2) ? Bh : Bl;
            const int org = (p < 2) ? row0 : col0;
            const uint32_t dstb = stb + p * 16384 + swoff;
            const __nv_bfloat16* s0 = src + (size_t)(org + lr) * K + kbase + lc * 8;
            CPA16(dstb, s0);
            CPA16(dstb + 8192, s0 + (size_t)64 * K);
        }
    };

    load_chunk(0, 0);
    CP_COMMIT();
    load_chunk(1, 64);
    CP_COMMIT();

    for (int kc = 0; kc < nchunk; kc++) {
        if (kc + 2 < nchunk) load_chunk((kc + 2) % 3, (kc + 2) * 64);
        CP_COMMIT();
        CP_WAIT2();
        __syncthreads();

        const uint32_t stb = sb + (kc % 3) * 65536;
#pragma unroll
        for (int k16 = 0; k16 < 4; k16++) {
            const uint32_t xk = ((uint32_t)(k16 << 5) + fkg) ^ fxor;
            uint32_t ah[2][4], al[2][4], bh[4][2], bl[4][2];
#pragma unroll
            for (int mt = 0; mt < 2; mt++) {
                LDSM4(ah[mt], stb + offA[mt] + xk);
                LDSM4(al[mt], stb + 16384 + offA[mt] + xk);
            }
#pragma unroll
            for (int ng = 0; ng < 2; ng++) {
                uint32_t q[4];
                LDSM4(q, stb + 32768 + offB[ng] + xk);
                bh[2 * ng][0] = q[0]; bh[2 * ng][1] = q[2];
                bh[2 * ng + 1][0] = q[1]; bh[2 * ng + 1][1] = q[3];
                LDSM4(q, stb + 49152 + offB[ng] + xk);
                bl[2 * ng][0] = q[0]; bl[2 * ng][1] = q[2];
                bl[2 * ng + 1][0] = q[1]; bl[2 * ng + 1][1] = q[3];
            }
#pragma unroll
            for (int mt = 0; mt < 2; mt++)
#pragma unroll
                for (int nt = 0; nt < 4; nt++) {
                    MMA_BF16(acc[mt][nt], ah[mt], bh[nt]);
                    MMA_BF16(acc[mt][nt], ah[mt], bl[nt]);
                    MMA_BF16(acc[mt][nt], al[mt], bh[nt]);
                }
        }
        __syncthreads();
    }

    const int erow = row0 + wr * 32 + (lane >> 2);
    const int ecol0 = col0 + wc * 32 + (lane & 3) * 2;
#pragma unroll
    for (int mt = 0; mt < 2; mt++) {
        const int r0 = erow + mt * 16;
#pragma unroll
        for (int nt = 0; nt < 4; nt++) {
            const size_t i0 = (size_t)r0 * N + ecol0 + nt * 8;
            const size_t i8 = i0 + (size_t)8 * N;
            float v0 = acc[mt][nt][0], v1 = acc[mt][nt][1];
            float v2 = acc[mt][nt][2], v3 = acc[mt][nt][3];
            if (BF16OUT) {
                uint32_t h01 = pack_bf16x2(v0, v1);
                uint32_t h23 = pack_bf16x2(v2, v3);
                __nv_bfloat162 b01 = *(__nv_bfloat162*)&h01;
                __nv_bfloat162 b23 = *(__nv_bfloat162*)&h23;
                *(uint32_t*)(Ch + i0) = h01;
                *(uint32_t*)(Ch + i8) = h23;
                *(uint32_t*)(Cl + i0) = pack_bf16x2(v0 - __bfloat162float(b01.x),
                                                    v1 - __bfloat162float(b01.y));
                *(uint32_t*)(Cl + i8) = pack_bf16x2(v2 - __bfloat162float(b23.x),
                                                    v3 - __bfloat162float(b23.y));
            } else {
                *(float2*)(Cf + i0) = make_float2(v0, v1);
                *(float2*)(Cf + i8) = make_float2(v2, v3);
            }
        }
    }
}

// ---------------------------------------------------------------------------
// Fused causal dual-attention via mma.sync — single-pass S phase.
//   Q tile 128 x 128 concat (resident smem). Key tile 64, 2-stage cp.async.
//   S bf16; softmax in exp2 domain; PV hi/lo fused per-k16 (low live regs).
// ---------------------------------------------------------------------------
#define ATTN_SMEM (32768 + 2 * 32768)

__global__ __launch_bounds__(256, 2) void attn_mma(
    const __nv_bfloat16* __restrict__ qkvh, const __nv_bfloat16* __restrict__ qkvl,
    const __nv_bfloat16* __restrict__ qgh,  const __nv_bfloat16* __restrict__ kgh,
    __nv_bfloat16* __restrict__ yh, __nv_bfloat16* __restrict__ yl)
{
    extern __shared__ char smem[];
    const uint32_t sb = smem_u32(smem);

    const int tid = threadIdx.x;
    const int wid = tid >> 5, lane = tid & 31;
    const int bhid = blockIdx.y, b = bhid >> 4, h = bhid & 15;
    const int qi = (int)gridDim.x - 1 - (int)blockIdx.x;  // heavy blocks first
    const int q0 = qi * 128;

    const __nv_bfloat16* qh = qkvh + (size_t)b * SEQ * (3 * DMODEL) + h * HDIM;
    const __nv_bfloat16* kh = qh + DMODEL;
    const __nv_bfloat16* vh = qh + 2 * DMODEL;
    const __nv_bfloat16* vl = qkvl + (size_t)b * SEQ * (3 * DMODEL) + h * HDIM + 2 * DMODEL;
    const __nv_bfloat16* qg = qgh + (size_t)b * SEQ * DMODEL + h * HDIM;
    const __nv_bfloat16* kg = kgh + (size_t)b * SEQ * DMODEL + h * HDIM;

    // ---- Q tile loads (cp.async): 128 rows x 256B, swizzled
    {
        const int c = tid & 15;
        const int rb = tid >> 4;
        const __nv_bfloat16* qsrc = (c < 8) ? qh + c * 8 : qg + (c - 8) * 8;
        const int qstr = (c < 8) ? 3 * DMODEL : DMODEL;
#pragma unroll
        for (int j = 0; j < 8; j++) {
            int r = rb + j * 16;
            uint32_t dst = sb + (uint32_t)(r * 256 + ((c ^ (r & 7)) << 4));
            CPA16(dst, qsrc + (size_t)(q0 + r) * qstr);
        }
    }

    auto load_kv = [&](int stage, int k0) {
        const uint32_t stb = sb + 32768 + stage * 32768;
        {
            const int c = tid & 15;
            const int rb = tid >> 4;
            const __nv_bfloat16* src = (c < 8) ? kh + c * 8 : kg + (c - 8) * 8;
            const int str = (c < 8) ? 3 * DMODEL : DMODEL;
#pragma unroll
            for (int j = 0; j < 4; j++) {
                int r = rb + j * 16;
                uint32_t dst = stb + (uint32_t)(r * 256 + ((c ^ (r & 7)) << 4));
                CPA16(dst, src + (size_t)(k0 + r) * str);
            }
        }
        {
            const int c = tid & 7;
            const int rb = tid >> 3;
#pragma unroll
            for (int j = 0; j < 2; j++) {
                int r = rb + j * 32;
                uint32_t off = (uint32_t)(r * 128 + ((c ^ (r & 7)) << 4));
                CPA16(stb + 16384 + off, vh + (size_t)(k0 + r) * (3 * DMODEL) + c * 8);
                CPA16(stb + 24576 + off, vl + (size_t)(k0 + r) * (3 * DMODEL) + c * 8);
            }
        }
    };

    load_kv(0, 0);
    CP_COMMIT();

    // ---- fragment addressing ----
    const int frow = (lane & 7) + ((lane >> 3) & 1) * 8;
    const uint32_t fxor = (uint32_t)((lane & 7) << 4);
    const uint32_t fkg  = (uint32_t)((lane >> 4) << 4);
    const uint32_t aQbase = sb + (uint32_t)((wid * 16 + frow) * 256);

    const int rowg = q0 + wid * 16 + (lane >> 2);
    float m0 = -1e30f, m1 = -1e30f, l0 = 0.0f, l1 = 0.0f;
    float o[8][4];
#pragma unroll
    for (int j = 0; j < 8; j++)
#pragma unroll
        for (int e = 0; e < 4; e++) o[j][e] = 0.0f;

    // scores pre-scaled into log2 domain: s' = s * SCALE * log2(e)
    const float SCALE2 = (0.125f / 7.6246189861593985f) * 1.4426950408889634f;
    const int ntiles = 2 * (qi + 1);

    for (int kt = 0; kt < ntiles; kt++) {
        const int k0 = kt * 64;
        if (kt + 1 < ntiles) load_kv((kt + 1) & 1, (kt + 1) * 64);
        CP_COMMIT();
        CP_WAIT1();
        __syncthreads();

        const uint32_t stb = sb + 32768 + (kt & 1) * 32768;

        // ---- S = Qc . Kc^T (16 x 64 per warp) — single pass
        float c[8][4];
#pragma unroll
        for (int j = 0; j < 8; j++)
#pragma unroll
            for (int e = 0; e < 4; e++) c[j][e] = 0.0f;

#pragma unroll
        for (int kd = 0; kd < 8; kd++) {
            const uint32_t xk = ((uint32_t)(kd << 5) + fkg) ^ fxor;
            uint32_t aq[4];
            LDSM4(aq, aQbase + xk);
#pragma unroll
            for (int g16 = 0; g16 < 4; g16++) {
                uint32_t q[4];
                LDSM4(q, stb + (uint32_t)((g16 * 16 + frow) * 256) + xk);
                uint32_t b0[2] = {q[0], q[2]};
                uint32_t b1[2] = {q[1], q[3]};
                MMA_BF16(c[2 * g16], aq, b0);
                MMA_BF16(c[2 * g16 + 1], aq, b1);
            }
        }

        // ---- scale (log2 domain) + mask + online softmax
        const bool need_mask = (k0 + 63 > rowg);  // per-lane: any col can exceed row
        float mx0 = -1e30f, mx1 = -1e30f;
#pragma unroll
        for (int j = 0; j < 8; j++) {
            int colb = k0 + j * 8 + (lane & 3) * 2;
#pragma unroll
            for (int e = 0; e < 4; e++) {
                float v = c[j][e] * SCALE2;
                if (need_mask) {
                    int col = colb + (e & 1);
                    int row = rowg + ((e >> 1) << 3);
                    if (col > row) v = -1e30f;
                }
                c[j][e] = v;
                if (e < 2) mx0 = fmaxf(mx0, v); else mx1 = fmaxf(mx1, v);
            }
        }
        mx0 = fmaxf(mx0, __shfl_xor_sync(0xffffffffu, mx0, 1));
        mx0 = fmaxf(mx0, __shfl_xor_sync(0xffffffffu, mx0, 2));
        mx1 = fmaxf(mx1, __shfl_xor_sync(0xffffffffu, mx1, 1));
        mx1 = fmaxf(mx1, __shfl_xor_sync(0xffffffffu, mx1, 2));
        float mn0 = fmaxf(m0, mx0), mn1 = fmaxf(m1, mx1);
        float cr0 = ex2f(m0 - mn0), cr1 = ex2f(m1 - mn1);
        m0 = mn0; m1 = mn1;

        float ls0 = 0.0f, ls1 = 0.0f;
#pragma unroll
        for (int j = 0; j < 8; j++) {
            c[j][0] = ex2f(c[j][0] - mn0);
            c[j][1] = ex2f(c[j][1] - mn0);
            c[j][2] = ex2f(c[j][2] - mn1);
            c[j][3] = ex2f(c[j][3] - mn1);
            ls0 += c[j][0] + c[j][1];
            ls1 += c[j][2] + c[j][3];
        }
        ls0 += __shfl_xor_sync(0xffffffffu, ls0, 1);
        ls0 += __shfl_xor_sync(0xffffffffu, ls0, 2);
        ls1 += __shfl_xor_sync(0xffffffffu, ls1, 1);
        ls1 += __shfl_xor_sync(0xffffffffu, ls1, 2);
        l0 = l0 * cr0 + ls0;
        l1 = l1 * cr1 + ls1;
#pragma unroll
        for (int j = 0; j < 8; j++) {
            o[j][0] *= cr0; o[j][1] *= cr0; o[j][2] *= cr1; o[j][3] *= cr1;
        }

        // ---- O += P.V, fused pack + MMA per k16 chunk (low live registers)
#pragma unroll
        for (int kk = 0; kk < 4; kk++) {
            uint32_t ph[4], pl[4];
#pragma unroll
            for (int half = 0; half < 2; half++) {
                const int j = 2 * kk + half;
                float p0 = c[j][0], p1 = c[j][1], p2 = c[j][2], p3 = c[j][3];
                uint32_t h01 = pack_bf16x2(p0, p1);
                uint32_t h23 = pack_bf16x2(p2, p3);
                __nv_bfloat162 hb01 = *(__nv_bfloat162*)&h01;
                __nv_bfloat162 hb23 = *(__nv_bfloat162*)&h23;
                ph[2 * half]     = h01;
                ph[2 * half + 1] = h23;
                pl[2 * half]     = pack_bf16x2(p0 - __bfloat162float(hb01.x),
                                               p1 - __bfloat162float(hb01.y));
                pl[2 * half + 1] = pack_bf16x2(p2 - __bfloat162float(hb23.x),
                                               p3 - __bfloat162float(hb23.y));
            }
            const uint32_t rowoff = (uint32_t)((kk * 16 + frow) * 128);
#pragma unroll
            for (int hb = 0; hb < 4; hb++) {
                const uint32_t xk = ((uint32_t)(hb << 5) + fkg) ^ fxor;
                uint32_t qv[4], rv[4];
                LDSM4T(qv, stb + 16384 + rowoff + xk);
                LDSM4T(rv, stb + 24576 + rowoff + xk);
                uint32_t bvh0[2] = {qv[0], qv[1]}, bvh1[2] = {qv[2], qv[3]};
                uint32_t bvl0[2] = {rv[0], rv[1]}, bvl1[2] = {rv[2], rv[3]};
                MMA_BF16(o[2 * hb],     ph, bvh0);
                MMA_BF16(o[2 * hb + 1], ph, bvh1);
                MMA_BF16(o[2 * hb],     ph, bvl0);
                MMA_BF16(o[2 * hb + 1], ph, bvl1);
                MMA_BF16(o[2 * hb],     pl, bvh0);
                MMA_BF16(o[2 * hb + 1], pl, bvh1);
            }
        }
        __syncthreads();
    }

    // ---- epilogue: normalize, hi/lo split, write yh/yl
    const float inv0 = 1.0f / l0, inv1 = 1.0f / l1;
    const size_t ybase = (size_t)b * SEQ * DMODEL + h * HDIM;
    const int ecol = (lane & 3) * 2;
    const int erow0 = q0 + wid * 16 + (lane >> 2);
#pragma unroll
    for (int j = 0; j < 8; j++) {
        float v0 = o[j][0] * inv0, v1 = o[j][1] * inv0;
        float v2 = o[j][2] * inv1, v3 = o[j][3] * inv1;
        size_t i0 = ybase + (size_t)erow0 * DMODEL + j * 8 + ecol;
        size_t i8 = i0 + (size_t)8 * DMODEL;
        uint32_t h01 = pack_bf16x2(v0, v1);
        uint32_t h23 = pack_bf16x2(v2, v3);
        __nv_bfloat162 hb01 = *(__nv_bfloat162*)&h01;
        __nv_bfloat162 hb23 = *(__nv_bfloat162*)&h23;
        *(uint32_t*)(yh + i0) = h01;
        *(uint32_t*)(yh + i8) = h23;
        *(uint32_t*)(yl + i0) = pack_bf16x2(v0 - __bfloat162float(hb01.x),
                                            v1 - __bfloat162float(hb01.y));
        *(uint32_t*)(yl + i8) = pack_bf16x2(v2 - __bfloat162float(hb23.x),
                                            v3 - __bfloat162float(hb23.y));
    }
}

// ---------------------------------------------------------------------------
extern "C" void kernel_launch(void* const* d_in, const int* in_sizes, int n_in,
                              void* d_out, int out_size)
{
    (void)in_sizes; (void)n_in; (void)out_size;
    const float* x     = (const float*)d_in[0];
    const float* q_g   = (const float*)d_in[1];
    const float* k_g   = (const float*)d_in[2];
    const float* W_qkv = (const float*)d_in[3];
    const float* W_out = (const float*)d_in[4];
    float* out = (float*)d_out;

    __nv_bfloat16 *qkvh, *qkvl, *xh, *xl, *yh, *yl, *qgh, *kgh;
    __nv_bfloat16 *wqh, *wql, *woh, *wol;
    cudaGetSymbolAddress((void**)&qkvh, g_qkvh);
    cudaGetSymbolAddress((void**)&qkvl, g_qkvl);
    cudaGetSymbolAddress((void**)&xh,  g_xh);
    cudaGetSymbolAddress((void**)&xl,  g_xl);
    cudaGetSymbolAddress((void**)&yh,  g_yh);
    cudaGetSymbolAddress((void**)&yl,  g_yl);
    cudaGetSymbolAddress((void**)&qgh, g_qgh);
    cudaGetSymbolAddress((void**)&kgh, g_kgh);
    cudaGetSymbolAddress((void**)&wqh, g_wqt_h);
    cudaGetSymbolAddress((void**)&wql, g_wqt_l);
    cudaGetSymbolAddress((void**)&woh, g_wot_h);
    cudaGetSymbolAddress((void**)&wol, g_wot_l);

    cudaFuncSetAttribute(gemm_mma<true>,  cudaFuncAttributeMaxDynamicSharedMemorySize,
                         GEMM_SMEM_BYTES);
    cudaFuncSetAttribute(gemm_mma<false>, cudaFuncAttributeMaxDynamicSharedMemorySize,
                         GEMM_SMEM_BYTES);
    cudaFuncSetAttribute(attn_mma, cudaFuncAttributeMaxDynamicSharedMemorySize,
                         ATTN_SMEM);

    const int M = BATCH * SEQ;
    const int n_elem = M * DMODEL;

    cvt_hilo<<<n_elem / 1024, 256>>>(x, xh, xl);
    cvt_bf16<<<n_elem / 1024, 256>>>(q_g, qgh);
    cvt_bf16<<<n_elem / 1024, 256>>>(k_g, kgh);
    tconv<<<dim3(3 * DMODEL / 32, DMODEL / 32), dim3(32, 8)>>>(W_qkv, wqh, wql,
                                                               DMODEL, 3 * DMODEL);
    tconv<<<dim3(DMODEL / 32, DMODEL / 32), dim3(32, 8)>>>(W_out, woh, wol,
                                                           DMODEL, DMODEL);

    gemm_mma<true><<<dim3(3 * DMODEL / 128, M / 128), 512, GEMM_SMEM_BYTES>>>(
        xh, xl, wqh, wql, nullptr, qkvh, qkvl, 3 * DMODEL, DMODEL);

    attn_mma<<<dim3(SEQ / 128, BATCH * NHEAD), 256, ATTN_SMEM>>>(
        qkvh, qkvl, qgh, kgh, yh, yl);

    gemm_mma<false><<<dim3(DMODEL / 128, M / 128), 512, GEMM_SMEM_BYTES>>>(
        yh, yl, woh, wol, out, nullptr, nullptr, DMODEL, DMODEL);
}

// round 15
// speedup vs baseline: 1.2081x; 1.2081x over previous
#include <cuda_runtime.h>
#include <cuda_bf16.h>
#include <cstdint>

#define BATCH  2
#define SEQ    2048
#define DMODEL 1024
#define NHEAD  16
#define HDIM   64

// ---------------------------------------------------------------------------
// Device-global scratch (allocation-free per harness rules)
// ---------------------------------------------------------------------------
static __device__ __nv_bfloat16 g_qkvh[(size_t)BATCH * SEQ * 3 * DMODEL]; // [4096,3072]
static __device__ __nv_bfloat16 g_qkvl[(size_t)BATCH * SEQ * 3 * DMODEL];
static __device__ float g_xt[(size_t)BATCH * SEQ * DMODEL];    // rna(x)
static __device__ float g_yf[(size_t)BATCH * SEQ * DMODEL];    // attn out (rna)
static __device__ __nv_bfloat16 g_qgh[(size_t)BATCH * SEQ * DMODEL];
static __device__ __nv_bfloat16 g_kgh[(size_t)BATCH * SEQ * DMODEL];
static __device__ float g_wqt[(size_t)3 * DMODEL * DMODEL];    // [3072,1024] (N,K) rna
static __device__ float g_wot[(size_t)DMODEL * DMODEL];        // [1024,1024] (N,K) rna

// ---------------------------------------------------------------------------
// Baseline-PTX helpers (legal for .target sm_103 — no 'a'-only features)
// ---------------------------------------------------------------------------
__device__ __forceinline__ uint32_t smem_u32(const void* p) {
    uint32_t a;
    asm("{ .reg .u64 t; cvta.to.shared.u64 t, %1; cvt.u32.u64 %0, t; }"
        : "=r"(a) : "l"(p));
    return a;
}

#define CPA16(dst, src) \
    asm volatile("cp.async.cg.shared.global [%0], [%1], 16;" \
                 :: "r"(dst), "l"(src) : "memory")
#define CP_COMMIT() asm volatile("cp.async.commit_group;" ::: "memory")
#define CP_WAIT1()  asm volatile("cp.async.wait_group 1;" ::: "memory")
#define CP_WAIT2()  asm volatile("cp.async.wait_group 2;" ::: "memory")

#define LDSM4(r, addr) \
    asm volatile("ldmatrix.sync.aligned.m8n8.x4.shared.b16 {%0,%1,%2,%3}, [%4];" \
                 : "=r"((r)[0]), "=r"((r)[1]), "=r"((r)[2]), "=r"((r)[3]) \
                 : "r"(addr))

#define LDSM4T(r, addr) \
    asm volatile("ldmatrix.sync.aligned.m8n8.x4.trans.shared.b16 {%0,%1,%2,%3}, [%4];" \
                 : "=r"((r)[0]), "=r"((r)[1]), "=r"((r)[2]), "=r"((r)[3]) \
                 : "r"(addr))

#define MMA_BF16(d, a, b) \
    asm volatile("mma.sync.aligned.m16n8k16.row.col.f32.bf16.bf16.f32 " \
                 "{%0,%1,%2,%3}, {%4,%5,%6,%7}, {%8,%9}, {%0,%1,%2,%3};" \
                 : "+f"((d)[0]), "+f"((d)[1]), "+f"((d)[2]), "+f"((d)[3]) \
                 : "r"((a)[0]), "r"((a)[1]), "r"((a)[2]), "r"((a)[3]), \
                   "r"((b)[0]), "r"((b)[1]))

#define MMA_TF32(d, a, b0, b1) \
    asm volatile("mma.sync.aligned.m16n8k8.row.col.f32.tf32.tf32.f32 " \
                 "{%0,%1,%2,%3}, {%4,%5,%6,%7}, {%8,%9}, {%0,%1,%2,%3};" \
                 : "+f"((d)[0]), "+f"((d)[1]), "+f"((d)[2]), "+f"((d)[3]) \
                 : "r"((a)[0]), "r"((a)[1]), "r"((a)[2]), "r"((a)[3]), \
                   "r"(b0), "r"(b1))

__device__ __forceinline__ uint32_t pack_bf16x2(float lo, float hi) {
    __nv_bfloat162 t = __floats2bfloat162_rn(lo, hi);
    return *(uint32_t*)&t;
}

__device__ __forceinline__ float ex2f(float x) {
    float y;
    asm("ex2.approx.ftz.f32 %0, %1;" : "=f"(y) : "f"(x));
    return y;
}

__device__ __forceinline__ float rna_tf32(float x) {
    uint32_t xi = __float_as_uint(x), yi;
    asm("cvt.rna.tf32.f32 %0, %1;" : "=r"(yi) : "r"(xi));
    return __uint_as_float(yi);
}

// ---------------------------------------------------------------------------
// Prep: fused elementwise — rna(x) -> xt ; q_g,k_g -> bf16
//   grid: [0,4096) x | [4096,8192) q_g | [8192,12288) k_g ; 4 elems/thread
// ---------------------------------------------------------------------------
__global__ __launch_bounds__(256) void prep_misc(
    const float* __restrict__ x, const float* __restrict__ q_g,
    const float* __restrict__ k_g,
    float* __restrict__ xt,
    __nv_bfloat16* __restrict__ qgh, __nv_bfloat16* __restrict__ kgh)
{
    int bx = blockIdx.x;
    if (bx < 4096) {
        int i = (bx * 256 + threadIdx.x) * 4;
        float4 v = *(const float4*)(x + i);
        *(float4*)(xt + i) = make_float4(rna_tf32(v.x), rna_tf32(v.y),
                                         rna_tf32(v.z), rna_tf32(v.w));
    } else if (bx < 8192) {
        int i = ((bx - 4096) * 256 + threadIdx.x) * 4;
        float4 v = *(const float4*)(q_g + i);
        *(uint2*)(qgh + i) = make_uint2(pack_bf16x2(v.x, v.y), pack_bf16x2(v.z, v.w));
    } else {
        int i = ((bx - 8192) * 256 + threadIdx.x) * 4;
        float4 v = *(const float4*)(k_g + i);
        *(uint2*)(kgh + i) = make_uint2(pack_bf16x2(v.x, v.y), pack_bf16x2(v.z, v.w));
    }
}

// Both weight transposes fused: W[K,N] fp32 -> Wt[N,K] fp32 (rna-rounded)
__global__ __launch_bounds__(256) void tconv2(const float* __restrict__ Wq,
                                              const float* __restrict__ Wo,
                                              float* __restrict__ Tq,
                                              float* __restrict__ To)
{
    __shared__ float t[32][33];
    const int tx = threadIdx.x, ty = threadIdx.y;
    const int bx = blockIdx.x;
    const float* W; float* T; int N, nb;
    if (bx < 96) { W = Wq; T = Tq; N = 3 * DMODEL; nb = bx; }
    else         { W = Wo; T = To; N = DMODEL;     nb = bx - 96; }
    const int K = DMODEL;
    const int k0 = blockIdx.y * 32, n0 = nb * 32;
#pragma unroll
    for (int r = ty; r < 32; r += 8)
        t[r][tx] = W[(size_t)(k0 + r) * N + n0 + tx];
    __syncthreads();
#pragma unroll
    for (int r = ty; r < 32; r += 8)
        T[(size_t)(n0 + r) * K + k0 + tx] = rna_tf32(t[tx][r]);
}

// ---------------------------------------------------------------------------
// tf32 GEMM via mma.sync: C[M,N] = A[M,K] * Bt[N,K]^T  (fp32 in, rna'd)
//   512 threads, 16 warps (4x4), warp tile 32x32. K chunks of 32 fp32 (128B
//   rows), 4-stage cp.async pipeline (128KB), 1 barrier/chunk.
//   Output fp32 OR bf16 hi/lo.
// ---------------------------------------------------------------------------
#define GEMM_SMEM_BYTES (4 * 32768)

template <bool BF16OUT>
__global__ __launch_bounds__(512, 1) void gemm_tf32(
    const float* __restrict__ A, const float* __restrict__ Bt,
    float* __restrict__ Cf,
    __nv_bfloat16* __restrict__ Ch, __nv_bfloat16* __restrict__ Cl,
    int N, int K)
{
    extern __shared__ char smem[];
    const uint32_t sb = smem_u32(smem);
    const int tid  = threadIdx.x;
    const int wid  = tid >> 5;
    const int lane = tid & 31;
    const int wr = wid >> 2;           // 0..3 (32-row band)
    const int wc = wid & 3;            // 0..3 (32-col band)
    const int row0 = blockIdx.y * 128;
    const int col0 = blockIdx.x * 128;
    const int nchunk = K / 32;

    // loader: per tile (128 rows x 32 fp32 = 128B/row), thread -> row lr,
    // granules lc and lc+4 (16B each), SW128 swizzle
    const int lr = tid >> 2;           // 0..127
    const int lc = tid & 3;            // granule 0..3
    const uint32_t swA0 = (uint32_t)(lr * 128 + ((lc * 16) ^ ((lr & 7) << 4)));
    const uint32_t swA1 = (uint32_t)(lr * 128 + (((lc + 4) * 16) ^ ((lr & 7) << 4)));

    // A-fragment ldmatrix addressing (m16k8 tf32 = 4 8x4-fp32 blocks)
    const int frowA = (lane & 7) + ((lane >> 3) & 1) * 8;   // row within 16
    const uint32_t fkgA  = (uint32_t)((lane >> 4) << 4);    // k-halves 0/1
    const uint32_t fxorA = (uint32_t)((lane & 7) << 4);
    // B-fragment: one x4 covers two n8 tiles
    const int frowB = ((lane >> 4) << 3) + (lane & 7);      // n row within 16
    const uint32_t fkgB  = (uint32_t)(((lane >> 3) & 1) << 4);
    const uint32_t fxorB = (uint32_t)((lane & 7) << 4);

    float acc[2][4][4];
#pragma unroll
    for (int mt = 0; mt < 2; mt++)
#pragma unroll
        for (int nt = 0; nt < 4; nt++)
#pragma unroll
            for (int e = 0; e < 4; e++) acc[mt][nt][e] = 0.0f;

    auto load_chunk = [&](int stage, int kbase) {
        const uint32_t stb = sb + stage * 32768;
        const float* a0 = A  + (size_t)(row0 + lr) * K + kbase + lc * 4;
        const float* b0 = Bt + (size_t)(col0 + lr) * K + kbase + lc * 4;
        CPA16(stb + swA0, a0);
        CPA16(stb + swA1, a0 + 16);
        CPA16(stb + 16384 + swA0, b0);
        CPA16(stb + 16384 + swA1, b0 + 16);
    };

    load_chunk(0, 0);  CP_COMMIT();
    load_chunk(1, 32); CP_COMMIT();
    load_chunk(2, 64); CP_COMMIT();

    for (int kc = 0; kc < nchunk; kc++) {
        CP_WAIT2();          // chunk kc resident
        __syncthreads();     // everyone done with chunk kc-1 (stage reuse safe)
        if (kc + 3 < nchunk) load_chunk((kc + 3) & 3, (kc + 3) * 32);
        CP_COMMIT();

        const uint32_t sA = sb + (kc & 3) * 32768;
        const uint32_t sB = sA + 16384;
#pragma unroll
        for (int k8 = 0; k8 < 4; k8++) {
            const uint32_t xkA = ((uint32_t)(k8 << 5) + fkgA) ^ fxorA;
            const uint32_t xkB = ((uint32_t)(k8 << 5) + fkgB) ^ fxorB;
            uint32_t a[2][4], bq[2][4];
#pragma unroll
            for (int mt = 0; mt < 2; mt++)
                LDSM4(a[mt], sA + (uint32_t)((wr * 32 + mt * 16 + frowA) * 128) + xkA);
#pragma unroll
            for (int g = 0; g < 2; g++)
                LDSM4(bq[g], sB + (uint32_t)((wc * 32 + g * 16 + frowB) * 128) + xkB);
            // bq[g]: [0]=b0 tile(2g), [1]=b1 tile(2g), [2]=b0 tile(2g+1), [3]=b1
#pragma unroll
            for (int mt = 0; mt < 2; mt++)
#pragma unroll
                for (int nt = 0; nt < 4; nt++)
                    MMA_TF32(acc[mt][nt], a[mt],
                             bq[nt >> 1][(nt & 1) * 2], bq[nt >> 1][(nt & 1) * 2 + 1]);
        }
    }

    // epilogue
    const int erow = row0 + wr * 32 + (lane >> 2);
    const int ecol0 = col0 + wc * 32 + (lane & 3) * 2;
#pragma unroll
    for (int mt = 0; mt < 2; mt++) {
        const int r0 = erow + mt * 16;
#pragma unroll
        for (int nt = 0; nt < 4; nt++) {
            const size_t i0 = (size_t)r0 * N + ecol0 + nt * 8;
            const size_t i8 = i0 + (size_t)8 * N;
            float v0 = acc[mt][nt][0], v1 = acc[mt][nt][1];
            float v2 = acc[mt][nt][2], v3 = acc[mt][nt][3];
            if (BF16OUT) {
                uint32_t h01 = pack_bf16x2(v0, v1);
                uint32_t h23 = pack_bf16x2(v2, v3);
                __nv_bfloat162 b01 = *(__nv_bfloat162*)&h01;
                __nv_bfloat162 b23 = *(__nv_bfloat162*)&h23;
                *(uint32_t*)(Ch + i0) = h01;
                *(uint32_t*)(Ch + i8) = h23;
                *(uint32_t*)(Cl + i0) = pack_bf16x2(v0 - __bfloat162float(b01.x),
                                                    v1 - __bfloat162float(b01.y));
                *(uint32_t*)(Cl + i8) = pack_bf16x2(v2 - __bfloat162float(b23.x),
                                                    v3 - __bfloat162float(b23.y));
            } else {
                *(float2*)(Cf + i0) = make_float2(v0, v1);
                *(float2*)(Cf + i8) = make_float2(v2, v3);
            }
        }
    }
}

// ---------------------------------------------------------------------------
// Fused causal dual-attention via mma.sync (unchanged core from R14).
//   Epilogue now writes y fp32 (rna-rounded for tf32 GEMM2).
// ---------------------------------------------------------------------------
#define ATTN_SMEM (32768 + 2 * 32768)

__global__ __launch_bounds__(256, 2) void attn_mma(
    const __nv_bfloat16* __restrict__ qkvh, const __nv_bfloat16* __restrict__ qkvl,
    const __nv_bfloat16* __restrict__ qgh,  const __nv_bfloat16* __restrict__ kgh,
    float* __restrict__ yf)
{
    extern __shared__ char smem[];
    const uint32_t sb = smem_u32(smem);

    const int tid = threadIdx.x;
    const int wid = tid >> 5, lane = tid & 31;
    const int bhid = blockIdx.y, b = bhid >> 4, h = bhid & 15;
    const int qi = (int)gridDim.x - 1 - (int)blockIdx.x;  // heavy blocks first
    const int q0 = qi * 128;

    const __nv_bfloat16* qh = qkvh + (size_t)b * SEQ * (3 * DMODEL) + h * HDIM;
    const __nv_bfloat16* kh = qh + DMODEL;
    const __nv_bfloat16* vh = qh + 2 * DMODEL;
    const __nv_bfloat16* vl = qkvl + (size_t)b * SEQ * (3 * DMODEL) + h * HDIM + 2 * DMODEL;
    const __nv_bfloat16* qg = qgh + (size_t)b * SEQ * DMODEL + h * HDIM;
    const __nv_bfloat16* kg = kgh + (size_t)b * SEQ * DMODEL + h * HDIM;

    // ---- Q tile loads (cp.async): 128 rows x 256B, swizzled
    {
        const int c = tid & 15;
        const int rb = tid >> 4;
        const __nv_bfloat16* qsrc = (c < 8) ? qh + c * 8 : qg + (c - 8) * 8;
        const int qstr = (c < 8) ? 3 * DMODEL : DMODEL;
#pragma unroll
        for (int j = 0; j < 8; j++) {
            int r = rb + j * 16;
            uint32_t dst = sb + (uint32_t)(r * 256 + ((c ^ (r & 7)) << 4));
            CPA16(dst, qsrc + (size_t)(q0 + r) * qstr);
        }
    }

    auto load_kv = [&](int stage, int k0) {
        const uint32_t stb = sb + 32768 + stage * 32768;
        {
            const int c = tid & 15;
            const int rb = tid >> 4;
            const __nv_bfloat16* src = (c < 8) ? kh + c * 8 : kg + (c - 8) * 8;
            const int str = (c < 8) ? 3 * DMODEL : DMODEL;
#pragma unroll
            for (int j = 0; j < 4; j++) {
                int r = rb + j * 16;
                uint32_t dst = stb + (uint32_t)(r * 256 + ((c ^ (r & 7)) << 4));
                CPA16(dst, src + (size_t)(k0 + r) * str);
            }
        }
        {
            const int c = tid & 7;
            const int rb = tid >> 3;
#pragma unroll
            for (int j = 0; j < 2; j++) {
                int r = rb + j * 32;
                uint32_t off = (uint32_t)(r * 128 + ((c ^ (r & 7)) << 4));
                CPA16(stb + 16384 + off, vh + (size_t)(k0 + r) * (3 * DMODEL) + c * 8);
                CPA16(stb + 24576 + off, vl + (size_t)(k0 + r) * (3 * DMODEL) + c * 8);
            }
        }
    };

    load_kv(0, 0);
    CP_COMMIT();

    // ---- fragment addressing ----
    const int frow = (lane & 7) + ((lane >> 3) & 1) * 8;
    const uint32_t fxor = (uint32_t)((lane & 7) << 4);
    const uint32_t fkg  = (uint32_t)((lane >> 4) << 4);
    const uint32_t aQbase = sb + (uint32_t)((wid * 16 + frow) * 256);

    const int rowg = q0 + wid * 16 + (lane >> 2);
    float m0 = -1e30f, m1 = -1e30f, l0 = 0.0f, l1 = 0.0f;
    float o[8][4];
#pragma unroll
    for (int j = 0; j < 8; j++)
#pragma unroll
        for (int e = 0; e < 4; e++) o[j][e] = 0.0f;

    const float SCALE2 = (0.125f / 7.6246189861593985f) * 1.4426950408889634f;
    const int ntiles = 2 * (qi + 1);

    for (int kt = 0; kt < ntiles; kt++) {
        const int k0 = kt * 64;
        if (kt + 1 < ntiles) load_kv((kt + 1) & 1, (kt + 1) * 64);
        CP_COMMIT();
        CP_WAIT1();
        __syncthreads();

        const uint32_t stb = sb + 32768 + (kt & 1) * 32768;

        // ---- S = Qc . Kc^T (16 x 64 per warp)
        float c[8][4];
#pragma unroll
        for (int j = 0; j < 8; j++)
#pragma unroll
            for (int e = 0; e < 4; e++) c[j][e] = 0.0f;

#pragma unroll
        for (int kd = 0; kd < 8; kd++) {
            const uint32_t xk = ((uint32_t)(kd << 5) + fkg) ^ fxor;
            uint32_t aq[4];
            LDSM4(aq, aQbase + xk);
#pragma unroll
            for (int g16 = 0; g16 < 4; g16++) {
                uint32_t q[4];
                LDSM4(q, stb + (uint32_t)((g16 * 16 + frow) * 256) + xk);
                uint32_t b0[2] = {q[0], q[2]};
                uint32_t b1[2] = {q[1], q[3]};
                MMA_BF16(c[2 * g16], aq, b0);
                MMA_BF16(c[2 * g16 + 1], aq, b1);
            }
        }

        // ---- scale (log2 domain) + mask + online softmax
        const bool need_mask = (k0 + 63 > rowg);
        float mx0 = -1e30f, mx1 = -1e30f;
#pragma unroll
        for (int j = 0; j < 8; j++) {
            int colb = k0 + j * 8 + (lane & 3) * 2;
#pragma unroll
            for (int e = 0; e < 4; e++) {
                float v = c[j][e] * SCALE2;
                if (need_mask) {
                    int col = colb + (e & 1);
                    int row = rowg + ((e >> 1) << 3);
                    if (col > row) v = -1e30f;
                }
                c[j][e] = v;
                if (e < 2) mx0 = fmaxf(mx0, v); else mx1 = fmaxf(mx1, v);
            }
        }
        mx0 = fmaxf(mx0, __shfl_xor_sync(0xffffffffu, mx0, 1));
        mx0 = fmaxf(mx0, __shfl_xor_sync(0xffffffffu, mx0, 2));
        mx1 = fmaxf(mx1, __shfl_xor_sync(0xffffffffu, mx1, 1));
        mx1 = fmaxf(mx1, __shfl_xor_sync(0xffffffffu, mx1, 2));
        float mn0 = fmaxf(m0, mx0), mn1 = fmaxf(m1, mx1);
        float cr0 = ex2f(m0 - mn0), cr1 = ex2f(m1 - mn1);
        m0 = mn0; m1 = mn1;

        float ls0 = 0.0f, ls1 = 0.0f;
#pragma unroll
        for (int j = 0; j < 8; j++) {
            c[j][0] = ex2f(c[j][0] - mn0);
            c[j][1] = ex2f(c[j][1] - mn0);
            c[j][2] = ex2f(c[j][2] - mn1);
            c[j][3] = ex2f(c[j][3] - mn1);
            ls0 += c[j][0] + c[j][1];
            ls1 += c[j][2] + c[j][3];
        }
        ls0 += __shfl_xor_sync(0xffffffffu, ls0, 1);
        ls0 += __shfl_xor_sync(0xffffffffu, ls0, 2);
        ls1 += __shfl_xor_sync(0xffffffffu, ls1, 1);
        ls1 += __shfl_xor_sync(0xffffffffu, ls1, 2);
        l0 = l0 * cr0 + ls0;
        l1 = l1 * cr1 + ls1;
#pragma unroll
        for (int j = 0; j < 8; j++) {
            o[j][0] *= cr0; o[j][1] *= cr0; o[j][2] *= cr1; o[j][3] *= cr1;
        }

        // ---- O += P.V, fused pack + MMA per k16 chunk (low live registers)
#pragma unroll
        for (int kk = 0; kk < 4; kk++) {
            uint32_t ph[4], pl[4];
#pragma unroll
            for (int half = 0; half < 2; half++) {
                const int j = 2 * kk + half;
                float p0 = c[j][0], p1 = c[j][1], p2 = c[j][2], p3 = c[j][3];
                uint32_t h01 = pack_bf16x2(p0, p1);
                uint32_t h23 = pack_bf16x2(p2, p3);
                __nv_bfloat162 hb01 = *(__nv_bfloat162*)&h01;
                __nv_bfloat162 hb23 = *(__nv_bfloat162*)&h23;
                ph[2 * half]     = h01;
                ph[2 * half + 1] = h23;
                pl[2 * half]     = pack_bf16x2(p0 - __bfloat162float(hb01.x),
                                               p1 - __bfloat162float(hb01.y));
                pl[2 * half + 1] = pack_bf16x2(p2 - __bfloat162float(hb23.x),
                                               p3 - __bfloat162float(hb23.y));
            }
            const uint32_t rowoff = (uint32_t)((kk * 16 + frow) * 128);
#pragma unroll
            for (int hb = 0; hb < 4; hb++) {
                const uint32_t xk = ((uint32_t)(hb << 5) + fkg) ^ fxor;
                uint32_t qv[4], rv[4];
                LDSM4T(qv, stb + 16384 + rowoff + xk);
                LDSM4T(rv, stb + 24576 + rowoff + xk);
                uint32_t bvh0[2] = {qv[0], qv[1]}, bvh1[2] = {qv[2], qv[3]};
                uint32_t bvl0[2] = {rv[0], rv[1]}, bvl1[2] = {rv[2], rv[3]};
                MMA_BF16(o[2 * hb],     ph, bvh0);
                MMA_BF16(o[2 * hb + 1], ph, bvh1);
                MMA_BF16(o[2 * hb],     ph, bvl0);
                MMA_BF16(o[2 * hb + 1], ph, bvl1);
                MMA_BF16(o[2 * hb],     pl, bvh0);
                MMA_BF16(o[2 * hb + 1], pl, bvh1);
            }
        }
        __syncthreads();
    }

    // ---- epilogue: normalize, rna-round, write y fp32
    const float inv0 = 1.0f / l0, inv1 = 1.0f / l1;
    const size_t ybase = (size_t)b * SEQ * DMODEL + h * HDIM;
    const int ecol = (lane & 3) * 2;
    const int erow0 = q0 + wid * 16 + (lane >> 2);
#pragma unroll
    for (int j = 0; j < 8; j++) {
        size_t i0 = ybase + (size_t)erow0 * DMODEL + j * 8 + ecol;
        size_t i8 = i0 + (size_t)8 * DMODEL;
        *(float2*)(yf + i0) = make_float2(rna_tf32(o[j][0] * inv0),
                                          rna_tf32(o[j][1] * inv0));
        *(float2*)(yf + i8) = make_float2(rna_tf32(o[j][2] * inv1),
                                          rna_tf32(o[j][3] * inv1));
    }
}

// ---------------------------------------------------------------------------
extern "C" void kernel_launch(void* const* d_in, const int* in_sizes, int n_in,
                              void* d_out, int out_size)
{
    (void)in_sizes; (void)n_in; (void)out_size;
    const float* x     = (const float*)d_in[0];
    const float* q_g   = (const float*)d_in[1];
    const float* k_g   = (const float*)d_in[2];
    const float* W_qkv = (const float*)d_in[3];
    const float* W_out = (const float*)d_in[4];
    float* out = (float*)d_out;

    __nv_bfloat16 *qkvh, *qkvl, *qgh, *kgh;
    float *xt, *yf, *wqt, *wot;
    cudaGetSymbolAddress((void**)&qkvh, g_qkvh);
    cudaGetSymbolAddress((void**)&qkvl, g_qkvl);
    cudaGetSymbolAddress((void**)&xt,  g_xt);
    cudaGetSymbolAddress((void**)&yf,  g_yf);
    cudaGetSymbolAddress((void**)&qgh, g_qgh);
    cudaGetSymbolAddress((void**)&kgh, g_kgh);
    cudaGetSymbolAddress((void**)&wqt, g_wqt);
    cudaGetSymbolAddress((void**)&wot, g_wot);

    cudaFuncSetAttribute(gemm_tf32<true>,  cudaFuncAttributeMaxDynamicSharedMemorySize,
                         GEMM_SMEM_BYTES);
    cudaFuncSetAttribute(gemm_tf32<false>, cudaFuncAttributeMaxDynamicSharedMemorySize,
                         GEMM_SMEM_BYTES);
    cudaFuncSetAttribute(attn_mma, cudaFuncAttributeMaxDynamicSharedMemorySize,
                         ATTN_SMEM);

    const int M = BATCH * SEQ;   // 4096

    // 1) fused elementwise prep
    prep_misc<<<12288, 256>>>(x, q_g, k_g, xt, qgh, kgh);
    // 2) both weight transposes (rna)
    tconv2<<<dim3(128, 32), dim3(32, 8)>>>(W_qkv, W_out, wqt, wot);
    // 3) qkv = x @ W_qkv  (tf32 MMA, bf16 hi/lo out)
    gemm_tf32<true><<<dim3(3 * DMODEL / 128, M / 128), 512, GEMM_SMEM_BYTES>>>(
        xt, wqt, nullptr, qkvh, qkvl, 3 * DMODEL, DMODEL);
    // 4) fused dual attention -> y fp32   (launch #4 — profiled)
    attn_mma<<<dim3(SEQ / 128, BATCH * NHEAD), 256, ATTN_SMEM>>>(
        qkvh, qkvl, qgh, kgh, yf);
    // 5) out = y @ W_out (tf32 MMA, fp32 out)
    gemm_tf32<false><<<dim3(DMODEL / 128, M / 128), 512, GEMM_SMEM_BYTES>>>(
        yf, wot, out, nullptr, nullptr, DMODEL, DMODEL);
}